// round 14
// baseline (speedup 1.0000x reference)
#include <cuda_runtime.h>
#include <cuda_fp16.h>
#include <cstdint>

// ---------------------------------------------------------------------------
// ProtoNet: out[q,c] = -||z_q - proto_c||^2
//   z_q   = xq @ W + b   (fp16 m16n8k16 mma, fp32 accum, cp.async pipeline)
//   proto = (classsum(xs)/cnt) @ W + b   (tf32 mma.sync, split-K)
//   out   = 2*z.proto^T - ||z||^2 - ||proto||^2   (accumulated via red.add
//           directly into d_out by each column-chunk CTA)
// 4 launches: mega-prep -> proto_tc -> proto_fin -> gemm_fused(+epilogue)
// Shapes: S=1024, Q=16384, F=2048, D=512, NWAY=64
// ---------------------------------------------------------------------------

#define NWAY 64
#define Q_MAX 16384
#define F_MAX 2048
#define NC 4              // D / 128 column chunks
#define NSLAB 8           // S split for class sums

__device__ __half g_xq16[(size_t)Q_MAX * F_MAX];          // 64 MB
__device__ __half g_w16[F_MAX * 512];                     // 2 MB
__device__ float g_cls_part[NSLAB * NWAY * F_MAX];        // 4 MB
__device__ float g_proto[NWAY * 512];                     // 128 KB
__device__ float g_pnorm[NWAY];
__device__ float g_invcnt[NWAY];
__device__ int   g_cnt[NWAY];

// single dynamic-smem symbol shared by all kernels
extern __shared__ char dyn_smem[];

// ---------------------------------------------------------------------------
// helpers
// ---------------------------------------------------------------------------
__device__ __forceinline__ float f2tf32(float x) {
    unsigned u;
    asm("cvt.rna.tf32.f32 %0, %1;" : "=r"(u) : "f"(x));
    return __uint_as_float(u);
}

__device__ __forceinline__ void mma8(float* d, const float* a, const float* b) {
    const unsigned* A = reinterpret_cast<const unsigned*>(a);
    const unsigned* B = reinterpret_cast<const unsigned*>(b);
    asm volatile(
        "mma.sync.aligned.m16n8k8.row.col.f32.tf32.tf32.f32 "
        "{%0,%1,%2,%3}, {%4,%5,%6,%7}, {%8,%9}, {%0,%1,%2,%3};\n"
        : "+f"(d[0]), "+f"(d[1]), "+f"(d[2]), "+f"(d[3])
        : "r"(A[0]), "r"(A[1]), "r"(A[2]), "r"(A[3]), "r"(B[0]), "r"(B[1]));
}

__device__ __forceinline__ void mma16(float* d, const uint32_t* a,
                                      const uint32_t* b) {
    asm volatile(
        "mma.sync.aligned.m16n8k16.row.col.f32.f16.f16.f32 "
        "{%0,%1,%2,%3}, {%4,%5,%6,%7}, {%8,%9}, {%0,%1,%2,%3};\n"
        : "+f"(d[0]), "+f"(d[1]), "+f"(d[2]), "+f"(d[3])
        : "r"(a[0]), "r"(a[1]), "r"(a[2]), "r"(a[3]), "r"(b[0]), "r"(b[1]));
}

#define LDSM_X4(r, addr)                                                      \
    asm volatile("ldmatrix.sync.aligned.m8n8.x4.shared.b16 {%0,%1,%2,%3}, [%4];" \
                 : "=r"((r)[0]), "=r"((r)[1]), "=r"((r)[2]), "=r"((r)[3])     \
                 : "r"(addr))

#define LDSM_X2T(r, addr)                                                     \
    asm volatile("ldmatrix.sync.aligned.m8n8.x2.trans.shared.b16 {%0,%1}, [%2];" \
                 : "=r"((r)[0]), "=r"((r)[1]) : "r"(addr))

#define CP_ASYNC16(dst, src)                                                  \
    asm volatile("cp.async.cg.shared.global [%0], [%1], 16;"                  \
                 :: "r"(dst), "l"(src) : "memory")
#define CP_COMMIT() asm volatile("cp.async.commit_group;" ::: "memory")
#define CP_WAIT2()  asm volatile("cp.async.wait_group 2;" ::: "memory")

__device__ __forceinline__ uint32_t smem_u32(const void* p) {
    uint32_t a;
    asm("{ .reg .u64 t; cvta.to.shared.u64 t, %1; cvt.u32.u64 %0, t; }"
        : "=r"(a) : "l"(p));
    return a;
}

__device__ __forceinline__ void cvt8_store(const float* x, __half* y,
                                           size_t idx) {
    const float4* p = (const float4*)x + idx * 2;
    float4 a = p[0], b = p[1];
    __half2 h[4];
    h[0] = __floats2half2_rn(a.x, a.y);
    h[1] = __floats2half2_rn(a.z, a.w);
    h[2] = __floats2half2_rn(b.x, b.y);
    h[3] = __floats2half2_rn(b.z, b.w);
    *(uint4*)(y + idx * 8) = *(uint4*)h;
}

// ---------------------------------------------------------------------------
// k_mega1: ONE launch doing all independent prep work, dispatched by block:
//   [0, nbCls)            class partial sums (per (slice, f-block), no atomics)
//   nbCls                 label counts -> cnt, invcnt
//   (+1, +nbZp]           zero proto
//   (.., +nbZo]           zero d_out
//   (.., +nbCq]           cvt xq -> fp16
//   rest                  cvt W -> fp16
// dyn smem: acc 64x256 f32 (65536 B) + ys slice 128 int + flag
// ---------------------------------------------------------------------------
#define MEGA_SMEM 66560

__global__ __launch_bounds__(256) void k_mega1(
    const float* __restrict__ xq, __half* __restrict__ xq16, int n8q,
    const float* __restrict__ Wf, __half* __restrict__ w16, int n8w,
    const float* __restrict__ xs, const void* __restrict__ ys, int S, int F,
    float* __restrict__ cls_part,
    float* __restrict__ proto, int protoQ4,
    float* __restrict__ out, int outQ4,
    int* __restrict__ cnt_out, float* __restrict__ invcnt,
    int nbCls, int nbZp, int nbZo, int nbCq)
{
    char* sm = dyn_smem;
    int bx = blockIdx.x, tid = threadIdx.x;

    if (bx < nbCls) {                       // ---- class partial sums ----
        float* acc = (float*)sm;            // [64][256]
        int* sys = (int*)(sm + 65536);      // [128]
        int* flag = sys + 128;
        int slice = bx & (NSLAB - 1), fb = bx >> 3;
        int chunk = S / NSLAB, s0 = slice * chunk;

        if (tid == 0) *flag = 0;
        __syncthreads();
        const int* w32 = (const int*)ys;
        for (int j = 1 + 2 * tid; j < S; j += 512)
            if (w32[j] != 0) *flag = 1;     // benign race
        __syncthreads();
        int is64 = !*flag;
        const long long* w64 = (const long long*)ys;
        for (int i = tid; i < chunk; i += 256)
            sys[i] = is64 ? (int)w64[s0 + i] : w32[s0 + i];
        #pragma unroll
        for (int c = 0; c < NWAY; c++) acc[c * 256 + tid] = 0.0f;
        __syncthreads();

        int f = fb * 256 + tid;
        #pragma unroll 4
        for (int i = 0; i < chunk; i++)
            acc[sys[i] * 256 + tid] += xs[(size_t)(s0 + i) * F + f];

        #pragma unroll
        for (int c = 0; c < NWAY; c++)
            cls_part[(size_t)(slice * NWAY + c) * F + f] = acc[c * 256 + tid];
        return;
    }
    bx -= nbCls;
    if (bx == 0) {                          // ---- label counts ----
        int* scnt = (int*)sm;
        int* flag = scnt + NWAY;
        if (tid == 0) *flag = 0;
        if (tid < NWAY) scnt[tid] = 0;
        __syncthreads();
        const int* w32 = (const int*)ys;
        for (int j = 1 + 2 * tid; j < S; j += 512)
            if (w32[j] != 0) *flag = 1;
        __syncthreads();
        int is64 = !*flag;
        const long long* w64 = (const long long*)ys;
        for (int i = tid; i < S; i += 256) {
            int c = is64 ? (int)w64[i] : w32[i];
            atomicAdd(&scnt[c], 1);
        }
        __syncthreads();
        if (tid < NWAY) {
            int c = scnt[tid];
            cnt_out[tid] = c;
            invcnt[tid] = 1.0f / (float)(c > 0 ? c : 1);
        }
        return;
    }
    bx -= 1;
    if (bx < nbZp) {                        // ---- zero proto ----
        int idx = bx * 256 + tid;
        if (idx < protoQ4)
            ((float4*)proto)[idx] = make_float4(0.f, 0.f, 0.f, 0.f);
        return;
    }
    bx -= nbZp;
    if (bx < nbZo) {                        // ---- zero out ----
        int idx = bx * 256 + tid;
        if (idx < outQ4)
            ((float4*)out)[idx] = make_float4(0.f, 0.f, 0.f, 0.f);
        return;
    }
    bx -= nbZo;
    if (bx < nbCq) {                        // ---- cvt xq ----
        size_t i = (size_t)bx * 256 + tid;
        if (i < (size_t)n8q) cvt8_store(xq, xq16, i);
        return;
    }
    bx -= nbCq;
    {                                       // ---- cvt W ----
        size_t i = (size_t)bx * 256 + tid;
        if (i < (size_t)n8w) cvt8_store(Wf, w16, i);
    }
}

// ---------------------------------------------------------------------------
// k_proto_tc: proto += (Σ_slab cls_part) @ W tile, tf32 mma.sync, split-K.
// (invcnt scaling deferred to k_proto_fin — linear, equivalent)
// ---------------------------------------------------------------------------
#define PAS 132
#define PWS 136
#define PROTO_SMEM_FLOATS (64 * PAS + 128 * PWS)

__global__ __launch_bounds__(256) void k_proto_tc(
    const float* __restrict__ cls_part, const float* __restrict__ W,
    float* __restrict__ proto, int F, int D)
{
    float* smf = (float*)dyn_smem;
    float* As = smf;
    float* Ws = smf + 64 * PAS;

    int tid  = threadIdx.x;
    int warp = tid >> 5, lane = tid & 31;
    int wm = warp & 1;
    int wn = warp >> 1;
    int colBase = blockIdx.x * 128;
    int k0 = blockIdx.y * 128;

    {   // A slice: 64 rows x 128 k, summed over NSLAB slabs, tf32
        int row = tid >> 2;
        int kp  = (tid & 3) * 32;
        const float* ap = cls_part + (size_t)row * F + k0 + kp;
        const size_t slab = (size_t)NWAY * F;
        #pragma unroll
        for (int j = 0; j < 8; j++) {
            float4 v = make_float4(0.f, 0.f, 0.f, 0.f);
            #pragma unroll
            for (int s = 0; s < NSLAB; s++) {
                float4 u = *(const float4*)(ap + s * slab + j * 4);
                v.x += u.x; v.y += u.y; v.z += u.z; v.w += u.w;
            }
            float4 t;
            t.x = f2tf32(v.x); t.y = f2tf32(v.y);
            t.z = f2tf32(v.z); t.w = f2tf32(v.w);
            *(float4*)&As[row * PAS + kp + j * 4] = t;
        }
    }
    {   // W slice: 128 k x 128 cols, tf32
        int kr = tid >> 1;
        int cp = (tid & 1) * 64;
        const float* wp = W + (size_t)(k0 + kr) * D + colBase + cp;
        #pragma unroll
        for (int j = 0; j < 16; j++) {
            float4 v = *(const float4*)(wp + j * 4);
            float4 t;
            t.x = f2tf32(v.x); t.y = f2tf32(v.y);
            t.z = f2tf32(v.z); t.w = f2tf32(v.w);
            *(float4*)&Ws[kr * PWS + cp + j * 4] = t;
        }
    }
    __syncthreads();

    int lg = lane >> 2;
    int lq = lane & 3;

    float acc[2][4][4];
    #pragma unroll
    for (int i = 0; i < 2; i++)
        #pragma unroll
        for (int j = 0; j < 4; j++)
            #pragma unroll
            for (int r = 0; r < 4; r++) acc[i][j][r] = 0.0f;

    int aoff[2], boff[4];
    #pragma unroll
    for (int mt = 0; mt < 2; mt++)
        aoff[mt] = (wm * 32 + mt * 16 + lg) * PAS + lq;
    #pragma unroll
    for (int nt = 0; nt < 4; nt++)
        boff[nt] = lq * PWS + wn * 32 + nt * 8 + lg;

    #pragma unroll 4
    for (int kk = 0; kk < 128; kk += 8) {
        float af[2][4], bf[4][2];
        #pragma unroll
        for (int mt = 0; mt < 2; mt++) {
            const float* base = &As[aoff[mt] + kk];
            af[mt][0] = base[0];
            af[mt][1] = base[8 * PAS];
            af[mt][2] = base[4];
            af[mt][3] = base[8 * PAS + 4];
        }
        #pragma unroll
        for (int nt = 0; nt < 4; nt++) {
            const float* base = &Ws[boff[nt] + kk * PWS];
            bf[nt][0] = base[0];
            bf[nt][1] = base[4 * PWS];
        }
        #pragma unroll
        for (int mt = 0; mt < 2; mt++)
            #pragma unroll
            for (int nt = 0; nt < 4; nt++)
                mma8(acc[mt][nt], af[mt], bf[nt]);
    }

    #pragma unroll
    for (int mt = 0; mt < 2; mt++) {
        int r = wm * 32 + mt * 16 + lg;
        #pragma unroll
        for (int nt = 0; nt < 4; nt++) {
            int d = colBase + wn * 32 + nt * 8 + lq * 2;
            atomicAdd(&proto[(size_t)r * D + d],       acc[mt][nt][0]);
            atomicAdd(&proto[(size_t)r * D + d + 1],   acc[mt][nt][1]);
            atomicAdd(&proto[(size_t)(r + 8) * D + d],     acc[mt][nt][2]);
            atomicAdd(&proto[(size_t)(r + 8) * D + d + 1], acc[mt][nt][3]);
        }
    }
}

// ---------------------------------------------------------------------------
// k_proto_fin: proto = proto*invcnt + bias (non-empty only), pnorm[c]
// ---------------------------------------------------------------------------
__global__ void k_proto_fin(float* __restrict__ proto,
                            const float* __restrict__ bias,
                            const int* __restrict__ cnt,
                            const float* __restrict__ invcnt,
                            float* __restrict__ pnorm, int D) {
    __shared__ float red[128];
    int c = blockIdx.x;
    int tid = threadIdx.x;
    bool nonempty = cnt[c] > 0;
    float ic = invcnt[c];
    float s = 0.f;
    for (int d = tid; d < D; d += blockDim.x) {
        float v = proto[(size_t)c * D + d] * ic + (nonempty ? bias[d] : 0.0f);
        proto[(size_t)c * D + d] = v;
        s = fmaf(v, v, s);
    }
    red[tid] = s;
    __syncthreads();
    for (int o = 64; o > 0; o >>= 1) {
        if (tid < o) red[tid] += red[tid + o];
        __syncthreads();
    }
    if (tid == 0) pnorm[c] = red[0];
}

// ---------------------------------------------------------------------------
// gemm_fused (fp16 + cp.async, single-barrier pipeline, fused final epilogue):
//   z = xq16 @ w16[:,chunk] + b       (m16n8k16, fp32 accum, 4-slot pipeline)
//   znorm_cx(row) reduced across the 4 col-strip warps in smem
//   out[q,c] += 2*(z@proto^T) - znorm_cx(q) - pnorm(c)/4   (red.add, out
//               pre-zeroed; the 4 cx chunks sum to the exact result)
// ---------------------------------------------------------------------------
#define BK 32
#define AS2 40      // halfs per A row (32 + 8) ; 80 B row = 16B-multiple
#define BS2 136     // halfs per B k-row (128 + 8) ; 272 B row
#define ZS2 136
#define PS2 72
#define A_BYTES (128 * AS2 * 2)     // 10240
#define B_BYTES (BK * BS2 * 2)      // 8704
#define OFF_B   (4 * A_BYTES)       // 40960
#define OFF_PS  75776
#define OFF_ZN  (OFF_PS + 128 * PS2 * 2)     // 94208
#define GEMM_SMEM (OFF_ZN + 128 * 4 * 4)     // 96256

__global__ __launch_bounds__(256, 2) void gemm_fused(
    const __half* __restrict__ A, const __half* __restrict__ Wh,
    const float* __restrict__ bias, const float* __restrict__ proto,
    const float* __restrict__ pnorm, float* __restrict__ out,
    int M, int N, int K)
{
    char* smraw = dyn_smem;
    const uint32_t sbase = smem_u32(smraw);

    int tid  = threadIdx.x;
    int warp = tid >> 5, lane = tid & 31;
    int wm = warp & 1;        // 0..1  (64-row half)
    int wn = warp >> 1;       // 0..3  (32-col strip)
    int cx = blockIdx.x;
    int rowBase = blockIdx.y * 128;
    int colBase = cx * 128;

    int aR[2], aO[2], bR[2], bO[2];
    #pragma unroll
    for (int j = 0; j < 2; j++) {
        int ch = tid + j * 256;
        aR[j] = ch >> 2;  aO[j] = (ch & 3) * 8;
        bR[j] = ch >> 4;  bO[j] = (ch & 15) * 8;
    }
    const __half* aG = A + (size_t)rowBase * K;
    const __half* bG = Wh + colBase;

    float acc[4][4][4];
    #pragma unroll
    for (int i = 0; i < 4; i++)
        #pragma unroll
        for (int j = 0; j < 4; j++)
            #pragma unroll
            for (int r = 0; r < 4; r++) acc[i][j][r] = 0.0f;

    int r16 = lane & 15, khalf = (lane >> 4) * 8;
    uint32_t aFragOff[4], bFragOff[4];
    #pragma unroll
    for (int mt = 0; mt < 4; mt++)
        aFragOff[mt] = (uint32_t)((wm * 64 + mt * 16 + r16) * AS2 + khalf) * 2;
    #pragma unroll
    for (int nt = 0; nt < 4; nt++)
        bFragOff[nt] = (uint32_t)(r16 * BS2 + wn * 32 + nt * 8) * 2;

    const int nIt = K / BK;   // 64

    // prologue: fill slots 0..2
    #pragma unroll
    for (int s = 0; s < 3; s++) {
        int k0 = s * BK;
        #pragma unroll
        for (int j = 0; j < 2; j++) {
            CP_ASYNC16(sbase + s * A_BYTES + (uint32_t)(aR[j] * AS2 + aO[j]) * 2,
                       aG + (size_t)aR[j] * K + k0 + aO[j]);
            CP_ASYNC16(sbase + OFF_B + s * B_BYTES + (uint32_t)(bR[j] * BS2 + bO[j]) * 2,
                       bG + (size_t)(k0 + bR[j]) * N + bO[j]);
        }
        CP_COMMIT();
    }

    // single-barrier mainloop
    for (int it = 0; it < nIt; ++it) {
        CP_WAIT2();
        __syncthreads();

        if (it + 3 < nIt) {
            int s = (it + 3) & 3;
            int k0 = (it + 3) * BK;
            #pragma unroll
            for (int j = 0; j < 2; j++) {
                CP_ASYNC16(sbase + s * A_BYTES + (uint32_t)(aR[j] * AS2 + aO[j]) * 2,
                           aG + (size_t)aR[j] * K + k0 + aO[j]);
                CP_ASYNC16(sbase + OFF_B + s * B_BYTES + (uint32_t)(bR[j] * BS2 + bO[j]) * 2,
                           bG + (size_t)(k0 + bR[j]) * N + bO[j]);
            }
        }
        CP_COMMIT();

        uint32_t aB = sbase + (it & 3) * A_BYTES;
        uint32_t bB = sbase + OFF_B + (it & 3) * B_BYTES;
        #pragma unroll
        for (int ks = 0; ks < 2; ks++) {
            uint32_t af[4][4], bf[4][2];
            #pragma unroll
            for (int mt = 0; mt < 4; mt++)
                LDSM_X4(af[mt], aB + aFragOff[mt] + ks * 32);
            #pragma unroll
            for (int nt = 0; nt < 4; nt++)
                LDSM_X2T(bf[nt], bB + bFragOff[nt] + ks * 16 * BS2 * 2);
            #pragma unroll
            for (int mt = 0; mt < 4; mt++)
                #pragma unroll
                for (int nt = 0; nt < 4; nt++)
                    mma16(acc[mt][nt], af[mt], bf[nt]);
        }
    }
    __syncthreads();   // all mma smem reads done before Zs overwrites

    __half* Zs = (__half*)smraw;
    __half* Ps = (__half*)(smraw + OFF_PS);
    float*  znsm = (float*)(smraw + OFF_ZN);   // [128][4]

    // fill Ps: proto[c][colBase..+128] -> Ps[d][c] fp16 (disjoint region)
    {
        int cc = tid >> 2;
        int dpart = (tid & 3) * 32;
        const float* pr = proto + (size_t)cc * N + colBase + dpart;
        #pragma unroll
        for (int j = 0; j < 8; j++) {
            float4 v = *(const float4*)(pr + j * 4);
            int d = dpart + j * 4;
            Ps[(d + 0) * PS2 + cc] = __float2half_rn(v.x);
            Ps[(d + 1) * PS2 + cc] = __float2half_rn(v.y);
            Ps[(d + 2) * PS2 + cc] = __float2half_rn(v.z);
            Ps[(d + 3) * PS2 + cc] = __float2half_rn(v.w);
        }
    }

    int lg = lane >> 2, lq = lane & 3;

    // epilogue 1: bias add, znorm strip-partials -> znsm, stage z fp16 -> Zs
    #pragma unroll
    for (int mt = 0; mt < 4; mt++) {
        int rl = wm * 64 + mt * 16 + lg;
        float sum0 = 0.f, sum1 = 0.f;
        #pragma unroll
        for (int nt = 0; nt < 4; nt++) {
            int cl = wn * 32 + nt * 8 + lq * 2;
            float bv0 = bias[colBase + cl], bv1 = bias[colBase + cl + 1];
            float v0 = acc[mt][nt][0] + bv0;
            float v1 = acc[mt][nt][1] + bv1;
            float v2 = acc[mt][nt][2] + bv0;
            float v3 = acc[mt][nt][3] + bv1;
            *(__half2*)&Zs[rl * ZS2 + cl]       = __floats2half2_rn(v0, v1);
            *(__half2*)&Zs[(rl + 8) * ZS2 + cl] = __floats2half2_rn(v2, v3);
            sum0 = fmaf(v0, v0, fmaf(v1, v1, sum0));
            sum1 = fmaf(v2, v2, fmaf(v3, v3, sum1));
        }
        sum0 += __shfl_xor_sync(0xFFFFFFFFu, sum0, 1);
        sum0 += __shfl_xor_sync(0xFFFFFFFFu, sum0, 2);
        sum1 += __shfl_xor_sync(0xFFFFFFFFu, sum1, 1);
        sum1 += __shfl_xor_sync(0xFFFFFFFFu, sum1, 2);
        if (lq == 0) {
            znsm[rl * 4 + wn]       = sum0;
            znsm[(rl + 8) * 4 + wn] = sum1;
        }
    }
    __syncthreads();

    // epilogue 2: cross = Zs[128x128] @ Ps^T -> red.add into out
    {
        float cacc[8][4];
        #pragma unroll
        for (int ct = 0; ct < 8; ct++)
            #pragma unroll
            for (int r = 0; r < 4; r++) cacc[ct][r] = 0.0f;

        uint32_t zlm = sbase + (uint32_t)((warp * 16 + r16) * ZS2 + khalf) * 2;
        uint32_t psBase = sbase + OFF_PS;

        #pragma unroll
        for (int kk = 0; kk < 8; kk++) {
            uint32_t afx[4];
            LDSM_X4(afx, zlm + kk * 32);
            #pragma unroll
            for (int ct = 0; ct < 8; ct++) {
                uint32_t bfx[2];
                LDSM_X2T(bfx, psBase +
                    (uint32_t)((kk * 16 + r16) * PS2 + ct * 8) * 2);
                mma16(cacc[ct], afx, bfx);
            }
        }

        int lr0 = warp * 16 + lg;
        float zn0 = znsm[lr0 * 4 + 0] + znsm[lr0 * 4 + 1] +
                    znsm[lr0 * 4 + 2] + znsm[lr0 * 4 + 3];
        float zn1 = znsm[(lr0 + 8) * 4 + 0] + znsm[(lr0 + 8) * 4 + 1] +
                    znsm[(lr0 + 8) * 4 + 2] + znsm[(lr0 + 8) * 4 + 3];

        int r0 = rowBase + lr0;
        #pragma unroll
        for (int ct = 0; ct < 8; ct++) {
            int col = ct * 8 + lq * 2;
            float p0 = 0.25f * pnorm[col];
            float p1 = 0.25f * pnorm[col + 1];
            atomicAdd(out + (size_t)r0 * NWAY + col,
                      2.0f * cacc[ct][0] - zn0 - p0);
            atomicAdd(out + (size_t)r0 * NWAY + col + 1,
                      2.0f * cacc[ct][1] - zn0 - p1);
            atomicAdd(out + (size_t)(r0 + 8) * NWAY + col,
                      2.0f * cacc[ct][2] - zn1 - p0);
            atomicAdd(out + (size_t)(r0 + 8) * NWAY + col + 1,
                      2.0f * cacc[ct][3] - zn1 - p1);
        }
    }
}

// ---------------------------------------------------------------------------
// Host launcher: 4 launches, all on the capture stream.
// ---------------------------------------------------------------------------
extern "C" void kernel_launch(void* const* d_in, const int* in_sizes, int n_in,
                              void* d_out, int out_size) {
    const float* xs = (const float*)d_in[0];
    const void*  ys = d_in[1];
    const float* xq = (const float*)d_in[2];
    const float* W  = (const float*)d_in[3];
    const float* b  = (const float*)d_in[4];

    int S = in_sizes[1];
    int F = in_sizes[0] / S;
    int D = in_sizes[4];
    int Q = in_sizes[2] / F;

    float *p_cls, *p_proto, *p_pnorm, *p_invcnt;
    __half *p_xq16, *p_w16;
    int *p_cnt;
    cudaGetSymbolAddress((void**)&p_cls, g_cls_part);
    cudaGetSymbolAddress((void**)&p_proto, g_proto);
    cudaGetSymbolAddress((void**)&p_pnorm, g_pnorm);
    cudaGetSymbolAddress((void**)&p_invcnt, g_invcnt);
    cudaGetSymbolAddress((void**)&p_cnt, g_cnt);
    cudaGetSymbolAddress((void**)&p_xq16, g_xq16);
    cudaGetSymbolAddress((void**)&p_w16, g_w16);

    cudaFuncSetAttribute(k_mega1,
                         cudaFuncAttributeMaxDynamicSharedMemorySize,
                         MEGA_SMEM);
    cudaFuncSetAttribute(k_proto_tc,
                         cudaFuncAttributeMaxDynamicSharedMemorySize,
                         PROTO_SMEM_FLOATS * 4);
    cudaFuncSetAttribute(gemm_fused,
                         cudaFuncAttributeMaxDynamicSharedMemorySize,
                         GEMM_SMEM);

    // 1. mega prep: cls partial sums + counts + zero proto/out + fp16 cvt
    int n8q = Q * F / 8, n8w = F * D / 8;
    int protoQ4 = NWAY * D / 4;
    int outQ4 = Q * NWAY / 4;
    int nbCls = (F / 256) * NSLAB;                 // 64
    int nbZp = (protoQ4 + 255) / 256;              // 32
    int nbZo = (outQ4 + 255) / 256;                // 1024
    int nbCq = (n8q + 255) / 256;                  // 16384
    int nbCw = (n8w + 255) / 256;                  // 512
    int nbTot = nbCls + 1 + nbZp + nbZo + nbCq + nbCw;
    k_mega1<<<nbTot, 256, MEGA_SMEM>>>(
        xq, p_xq16, n8q, W, p_w16, n8w, xs, ys, S, F,
        p_cls, p_proto, protoQ4, (float*)d_out, outQ4,
        p_cnt, p_invcnt, nbCls, nbZp, nbZo, nbCq);

    // 2. prototypes: proto = (Σ slabs) @ W  (tf32 tensor cores, split-K)
    {
        dim3 grid(D / 128, F / 128);
        k_proto_tc<<<grid, 256, PROTO_SMEM_FLOATS * 4>>>(
            p_cls, W, p_proto, F, D);
    }

    // 3. proto finalize: *invcnt, +bias (non-empty), pnorm
    k_proto_fin<<<NWAY, 128>>>(p_proto, b, p_cnt, p_invcnt, p_pnorm, D);

    // 4. fused fp16 GEMM + full epilogue (red.add into pre-zeroed out)
    {
        dim3 grid(NC, Q / 128);
        gemm_fused<<<grid, 256, GEMM_SMEM>>>(
            p_xq16, p_w16, b, p_proto, p_pnorm, (float*)d_out, Q, D, F);
    }
}

// round 15
// speedup vs baseline: 1.0409x; 1.0409x over previous
#include <cuda_runtime.h>
#include <cuda_fp16.h>
#include <cstdint>

// ---------------------------------------------------------------------------
// ProtoNet: out[q,c] = -||z_q - proto_c||^2
//   z_q   = xq @ W + b   (fp16 m16n8k16 mma, fp32 accum, cp.async 3-slot
//                         BK=64 pipeline; z never materialized to gmem)
//   proto = (classsum(xs)/cnt) @ W + b   (tf32 mma.sync, split-K)
//   out   = 2*z.proto^T - ||z||^2 - ||proto||^2  (red.add into d_out)
// 4 launches: mega-prep -> proto_tc -> proto_fin -> gemm_fused(+epilogue)
// Shapes: S=1024, Q=16384, F=2048, D=512, NWAY=64
// ---------------------------------------------------------------------------

#define NWAY 64
#define Q_MAX 16384
#define F_MAX 2048
#define NC 4              // D / 128 column chunks
#define NSLAB 8           // S split for class sums

__device__ __half g_xq16[(size_t)Q_MAX * F_MAX];          // 64 MB
__device__ __half g_w16[F_MAX * 512];                     // 2 MB
__device__ float g_cls_part[NSLAB * NWAY * F_MAX];        // 4 MB
__device__ float g_proto[NWAY * 512];                     // 128 KB
__device__ float g_pnorm[NWAY];
__device__ float g_invcnt[NWAY];
__device__ int   g_cnt[NWAY];

// single dynamic-smem symbol shared by all kernels
extern __shared__ char dyn_smem[];

// ---------------------------------------------------------------------------
// helpers
// ---------------------------------------------------------------------------
__device__ __forceinline__ float f2tf32(float x) {
    unsigned u;
    asm("cvt.rna.tf32.f32 %0, %1;" : "=r"(u) : "f"(x));
    return __uint_as_float(u);
}

__device__ __forceinline__ void mma8(float* d, const float* a, const float* b) {
    const unsigned* A = reinterpret_cast<const unsigned*>(a);
    const unsigned* B = reinterpret_cast<const unsigned*>(b);
    asm volatile(
        "mma.sync.aligned.m16n8k8.row.col.f32.tf32.tf32.f32 "
        "{%0,%1,%2,%3}, {%4,%5,%6,%7}, {%8,%9}, {%0,%1,%2,%3};\n"
        : "+f"(d[0]), "+f"(d[1]), "+f"(d[2]), "+f"(d[3])
        : "r"(A[0]), "r"(A[1]), "r"(A[2]), "r"(A[3]), "r"(B[0]), "r"(B[1]));
}

__device__ __forceinline__ void mma16(float* d, const uint32_t* a,
                                      const uint32_t* b) {
    asm volatile(
        "mma.sync.aligned.m16n8k16.row.col.f32.f16.f16.f32 "
        "{%0,%1,%2,%3}, {%4,%5,%6,%7}, {%8,%9}, {%0,%1,%2,%3};\n"
        : "+f"(d[0]), "+f"(d[1]), "+f"(d[2]), "+f"(d[3])
        : "r"(a[0]), "r"(a[1]), "r"(a[2]), "r"(a[3]), "r"(b[0]), "r"(b[1]));
}

#define LDSM_X4(r, addr)                                                      \
    asm volatile("ldmatrix.sync.aligned.m8n8.x4.shared.b16 {%0,%1,%2,%3}, [%4];" \
                 : "=r"((r)[0]), "=r"((r)[1]), "=r"((r)[2]), "=r"((r)[3])     \
                 : "r"(addr))

#define LDSM_X2T(r, addr)                                                     \
    asm volatile("ldmatrix.sync.aligned.m8n8.x2.trans.shared.b16 {%0,%1}, [%2];" \
                 : "=r"((r)[0]), "=r"((r)[1]) : "r"(addr))

#define CP_ASYNC16(dst, src)                                                  \
    asm volatile("cp.async.cg.shared.global [%0], [%1], 16;"                  \
                 :: "r"(dst), "l"(src) : "memory")
#define CP_COMMIT() asm volatile("cp.async.commit_group;" ::: "memory")
#define CP_WAIT1()  asm volatile("cp.async.wait_group 1;" ::: "memory")

__device__ __forceinline__ uint32_t smem_u32(const void* p) {
    uint32_t a;
    asm("{ .reg .u64 t; cvta.to.shared.u64 t, %1; cvt.u32.u64 %0, t; }"
        : "=r"(a) : "l"(p));
    return a;
}

__device__ __forceinline__ void cvt8_store(const float* x, __half* y,
                                           size_t idx) {
    const float4* p = (const float4*)x + idx * 2;
    float4 a = p[0], b = p[1];
    __half2 h[4];
    h[0] = __floats2half2_rn(a.x, a.y);
    h[1] = __floats2half2_rn(a.z, a.w);
    h[2] = __floats2half2_rn(b.x, b.y);
    h[3] = __floats2half2_rn(b.z, b.w);
    *(uint4*)(y + idx * 8) = *(uint4*)h;
}

// ---------------------------------------------------------------------------
// k_mega1: ONE launch doing all independent prep work, dispatched by block:
//   [0, nbCls)            class partial sums (per (slice, f-block), no atomics)
//   nbCls                 label counts -> cnt, invcnt
//   (+1, +nbZp]           zero proto
//   (.., +nbZo]           zero d_out
//   (.., +nbCq]           cvt xq -> fp16
//   rest                  cvt W -> fp16
// ---------------------------------------------------------------------------
#define MEGA_SMEM 66560

__global__ __launch_bounds__(256) void k_mega1(
    const float* __restrict__ xq, __half* __restrict__ xq16, int n8q,
    const float* __restrict__ Wf, __half* __restrict__ w16, int n8w,
    const float* __restrict__ xs, const void* __restrict__ ys, int S, int F,
    float* __restrict__ cls_part,
    float* __restrict__ proto, int protoQ4,
    float* __restrict__ out, int outQ4,
    int* __restrict__ cnt_out, float* __restrict__ invcnt,
    int nbCls, int nbZp, int nbZo, int nbCq)
{
    char* sm = dyn_smem;
    int bx = blockIdx.x, tid = threadIdx.x;

    if (bx < nbCls) {                       // ---- class partial sums ----
        float* acc = (float*)sm;            // [64][256]
        int* sys = (int*)(sm + 65536);      // [128]
        int* flag = sys + 128;
        int slice = bx & (NSLAB - 1), fb = bx >> 3;
        int chunk = S / NSLAB, s0 = slice * chunk;

        if (tid == 0) *flag = 0;
        __syncthreads();
        const int* w32 = (const int*)ys;
        for (int j = 1 + 2 * tid; j < S; j += 512)
            if (w32[j] != 0) *flag = 1;     // benign race
        __syncthreads();
        int is64 = !*flag;
        const long long* w64 = (const long long*)ys;
        for (int i = tid; i < chunk; i += 256)
            sys[i] = is64 ? (int)w64[s0 + i] : w32[s0 + i];
        #pragma unroll
        for (int c = 0; c < NWAY; c++) acc[c * 256 + tid] = 0.0f;
        __syncthreads();

        int f = fb * 256 + tid;
        #pragma unroll 4
        for (int i = 0; i < chunk; i++)
            acc[sys[i] * 256 + tid] += xs[(size_t)(s0 + i) * F + f];

        #pragma unroll
        for (int c = 0; c < NWAY; c++)
            cls_part[(size_t)(slice * NWAY + c) * F + f] = acc[c * 256 + tid];
        return;
    }
    bx -= nbCls;
    if (bx == 0) {                          // ---- label counts ----
        int* scnt = (int*)sm;
        int* flag = scnt + NWAY;
        if (tid == 0) *flag = 0;
        if (tid < NWAY) scnt[tid] = 0;
        __syncthreads();
        const int* w32 = (const int*)ys;
        for (int j = 1 + 2 * tid; j < S; j += 512)
            if (w32[j] != 0) *flag = 1;
        __syncthreads();
        int is64 = !*flag;
        const long long* w64 = (const long long*)ys;
        for (int i = tid; i < S; i += 256) {
            int c = is64 ? (int)w64[i] : w32[i];
            atomicAdd(&scnt[c], 1);
        }
        __syncthreads();
        if (tid < NWAY) {
            int c = scnt[tid];
            cnt_out[tid] = c;
            invcnt[tid] = 1.0f / (float)(c > 0 ? c : 1);
        }
        return;
    }
    bx -= 1;
    if (bx < nbZp) {                        // ---- zero proto ----
        int idx = bx * 256 + tid;
        if (idx < protoQ4)
            ((float4*)proto)[idx] = make_float4(0.f, 0.f, 0.f, 0.f);
        return;
    }
    bx -= nbZp;
    if (bx < nbZo) {                        // ---- zero out ----
        int idx = bx * 256 + tid;
        if (idx < outQ4)
            ((float4*)out)[idx] = make_float4(0.f, 0.f, 0.f, 0.f);
        return;
    }
    bx -= nbZo;
    if (bx < nbCq) {                        // ---- cvt xq ----
        size_t i = (size_t)bx * 256 + tid;
        if (i < (size_t)n8q) cvt8_store(xq, xq16, i);
        return;
    }
    bx -= nbCq;
    {                                       // ---- cvt W ----
        size_t i = (size_t)bx * 256 + tid;
        if (i < (size_t)n8w) cvt8_store(Wf, w16, i);
    }
}

// ---------------------------------------------------------------------------
// k_proto_tc: proto += (Σ_slab cls_part) @ W tile, tf32 mma.sync, split-K.
// ---------------------------------------------------------------------------
#define PAS 132
#define PWS 136
#define PROTO_SMEM_FLOATS (64 * PAS + 128 * PWS)

__global__ __launch_bounds__(256) void k_proto_tc(
    const float* __restrict__ cls_part, const float* __restrict__ W,
    float* __restrict__ proto, int F, int D)
{
    float* smf = (float*)dyn_smem;
    float* As = smf;
    float* Ws = smf + 64 * PAS;

    int tid  = threadIdx.x;
    int warp = tid >> 5, lane = tid & 31;
    int wm = warp & 1;
    int wn = warp >> 1;
    int colBase = blockIdx.x * 128;
    int k0 = blockIdx.y * 128;

    {   // A slice: 64 rows x 128 k, summed over NSLAB slabs, tf32
        int row = tid >> 2;
        int kp  = (tid & 3) * 32;
        const float* ap = cls_part + (size_t)row * F + k0 + kp;
        const size_t slab = (size_t)NWAY * F;
        #pragma unroll
        for (int j = 0; j < 8; j++) {
            float4 v = make_float4(0.f, 0.f, 0.f, 0.f);
            #pragma unroll
            for (int s = 0; s < NSLAB; s++) {
                float4 u = *(const float4*)(ap + s * slab + j * 4);
                v.x += u.x; v.y += u.y; v.z += u.z; v.w += u.w;
            }
            float4 t;
            t.x = f2tf32(v.x); t.y = f2tf32(v.y);
            t.z = f2tf32(v.z); t.w = f2tf32(v.w);
            *(float4*)&As[row * PAS + kp + j * 4] = t;
        }
    }
    {   // W slice: 128 k x 128 cols, tf32
        int kr = tid >> 1;
        int cp = (tid & 1) * 64;
        const float* wp = W + (size_t)(k0 + kr) * D + colBase + cp;
        #pragma unroll
        for (int j = 0; j < 16; j++) {
            float4 v = *(const float4*)(wp + j * 4);
            float4 t;
            t.x = f2tf32(v.x); t.y = f2tf32(v.y);
            t.z = f2tf32(v.z); t.w = f2tf32(v.w);
            *(float4*)&Ws[kr * PWS + cp + j * 4] = t;
        }
    }
    __syncthreads();

    int lg = lane >> 2;
    int lq = lane & 3;

    float acc[2][4][4];
    #pragma unroll
    for (int i = 0; i < 2; i++)
        #pragma unroll
        for (int j = 0; j < 4; j++)
            #pragma unroll
            for (int r = 0; r < 4; r++) acc[i][j][r] = 0.0f;

    int aoff[2], boff[4];
    #pragma unroll
    for (int mt = 0; mt < 2; mt++)
        aoff[mt] = (wm * 32 + mt * 16 + lg) * PAS + lq;
    #pragma unroll
    for (int nt = 0; nt < 4; nt++)
        boff[nt] = lq * PWS + wn * 32 + nt * 8 + lg;

    #pragma unroll 4
    for (int kk = 0; kk < 128; kk += 8) {
        float af[2][4], bf[4][2];
        #pragma unroll
        for (int mt = 0; mt < 2; mt++) {
            const float* base = &As[aoff[mt] + kk];
            af[mt][0] = base[0];
            af[mt][1] = base[8 * PAS];
            af[mt][2] = base[4];
            af[mt][3] = base[8 * PAS + 4];
        }
        #pragma unroll
        for (int nt = 0; nt < 4; nt++) {
            const float* base = &Ws[boff[nt] + kk * PWS];
            bf[nt][0] = base[0];
            bf[nt][1] = base[4 * PWS];
        }
        #pragma unroll
        for (int mt = 0; mt < 2; mt++)
            #pragma unroll
            for (int nt = 0; nt < 4; nt++)
                mma8(acc[mt][nt], af[mt], bf[nt]);
    }

    #pragma unroll
    for (int mt = 0; mt < 2; mt++) {
        int r = wm * 32 + mt * 16 + lg;
        #pragma unroll
        for (int nt = 0; nt < 4; nt++) {
            int d = colBase + wn * 32 + nt * 8 + lq * 2;
            atomicAdd(&proto[(size_t)r * D + d],       acc[mt][nt][0]);
            atomicAdd(&proto[(size_t)r * D + d + 1],   acc[mt][nt][1]);
            atomicAdd(&proto[(size_t)(r + 8) * D + d],     acc[mt][nt][2]);
            atomicAdd(&proto[(size_t)(r + 8) * D + d + 1], acc[mt][nt][3]);
        }
    }
}

// ---------------------------------------------------------------------------
// k_proto_fin: proto = proto*invcnt + bias (non-empty only), pnorm[c]
// ---------------------------------------------------------------------------
__global__ void k_proto_fin(float* __restrict__ proto,
                            const float* __restrict__ bias,
                            const int* __restrict__ cnt,
                            const float* __restrict__ invcnt,
                            float* __restrict__ pnorm, int D) {
    __shared__ float red[128];
    int c = blockIdx.x;
    int tid = threadIdx.x;
    bool nonempty = cnt[c] > 0;
    float ic = invcnt[c];
    float s = 0.f;
    for (int d = tid; d < D; d += blockDim.x) {
        float v = proto[(size_t)c * D + d] * ic + (nonempty ? bias[d] : 0.0f);
        proto[(size_t)c * D + d] = v;
        s = fmaf(v, v, s);
    }
    red[tid] = s;
    __syncthreads();
    for (int o = 64; o > 0; o >>= 1) {
        if (tid < o) red[tid] += red[tid + o];
        __syncthreads();
    }
    if (tid == 0) pnorm[c] = red[0];
}

// ---------------------------------------------------------------------------
// gemm_fused: fp16 mma, BK=64, 3-slot cp.async pipeline (32 barriers total),
// fused final epilogue (red.add into pre-zeroed out).
// SMEM slots: slot s at s*SLOT_B: A 128x72h (18432 B) then B 64x136h (17408 B)
// Epilogue (overlaps slots): Zs 128x136h, Ps at 34816, znsm at 53248.
// ---------------------------------------------------------------------------
#define BK 64
#define AS2 72      // halfs per A row (64 + 8) ; 144 B row = 16B-multiple
#define BS2 136     // halfs per B k-row (128 + 8)
#define ZS2 136
#define PS2 72
#define A_BYTES (128 * AS2 * 2)     // 18432
#define B_BYTES (BK * BS2 * 2)      // 17408
#define SLOT_B  (A_BYTES + B_BYTES) // 35840
#define OFF_PS  34816
#define OFF_ZN  (OFF_PS + 128 * PS2 * 2)     // 53248
#define GEMM_SMEM (3 * SLOT_B)               // 107520

__global__ __launch_bounds__(256, 2) void gemm_fused(
    const __half* __restrict__ A, const __half* __restrict__ Wh,
    const float* __restrict__ bias, const float* __restrict__ proto,
    const float* __restrict__ pnorm, float* __restrict__ out,
    int M, int N, int K)
{
    char* smraw = dyn_smem;
    const uint32_t sbase = smem_u32(smraw);

    int tid  = threadIdx.x;
    int warp = tid >> 5, lane = tid & 31;
    int wm = warp & 1;        // 0..1  (64-row half)
    int wn = warp >> 1;       // 0..3  (32-col strip)
    int cx = blockIdx.x;
    int rowBase = blockIdx.y * 128;
    int colBase = cx * 128;

    // 4 x 16B cp.async per operand per thread per BK=64 chunk
    int aR[4], aO[4], bR[4], bO[4];
    #pragma unroll
    for (int j = 0; j < 4; j++) {
        int ch = tid + j * 256;
        aR[j] = ch >> 3;  aO[j] = (ch & 7) * 8;    // A: 128 rows x 8 chunks
        bR[j] = ch >> 4;  bO[j] = (ch & 15) * 8;   // B: 64 rows x 16 chunks
    }
    const __half* aG = A + (size_t)rowBase * K;
    const __half* bG = Wh + colBase;

    float acc[4][4][4];
    #pragma unroll
    for (int i = 0; i < 4; i++)
        #pragma unroll
        for (int j = 0; j < 4; j++)
            #pragma unroll
            for (int r = 0; r < 4; r++) acc[i][j][r] = 0.0f;

    int r16 = lane & 15, khalf = (lane >> 4) * 8;
    uint32_t aFragOff[4], bFragOff[4];
    #pragma unroll
    for (int mt = 0; mt < 4; mt++)
        aFragOff[mt] = (uint32_t)((wm * 64 + mt * 16 + r16) * AS2 + khalf) * 2;
    #pragma unroll
    for (int nt = 0; nt < 4; nt++)
        bFragOff[nt] = (uint32_t)(r16 * BS2 + wn * 32 + nt * 8) * 2;

    const int nIt = K / BK;   // 32

    // issue one BK=64 slot's loads
    auto issue_slot = [&](int slot, int k0) {
        uint32_t aBase = sbase + slot * SLOT_B;
        uint32_t bBase = aBase + A_BYTES;
        #pragma unroll
        for (int j = 0; j < 4; j++) {
            CP_ASYNC16(aBase + (uint32_t)(aR[j] * AS2 + aO[j]) * 2,
                       aG + (size_t)aR[j] * K + k0 + aO[j]);
            CP_ASYNC16(bBase + (uint32_t)(bR[j] * BS2 + bO[j]) * 2,
                       bG + (size_t)(k0 + bR[j]) * N + bO[j]);
        }
    };

    // prologue: fill slots 0,1
    issue_slot(0, 0);
    CP_COMMIT();
    issue_slot(1, BK);
    CP_COMMIT();

    int slot = 0;
    for (int it = 0; it < nIt; ++it) {
        CP_WAIT1();
        __syncthreads();

        if (it + 2 < nIt) {
            int s2 = slot + 2; if (s2 >= 3) s2 -= 3;
            issue_slot(s2, (it + 2) * BK);
        }
        CP_COMMIT();

        uint32_t aB = sbase + slot * SLOT_B;
        uint32_t bB = aB + A_BYTES;
        #pragma unroll
        for (int ks = 0; ks < 4; ks++) {       // four k16 steps in BK=64
            uint32_t af[4][4], bf[4][2];
            #pragma unroll
            for (int mt = 0; mt < 4; mt++)
                LDSM_X4(af[mt], aB + aFragOff[mt] + ks * 32);
            #pragma unroll
            for (int nt = 0; nt < 4; nt++)
                LDSM_X2T(bf[nt], bB + bFragOff[nt] + ks * 16 * BS2 * 2);
            #pragma unroll
            for (int mt = 0; mt < 4; mt++)
                #pragma unroll
                for (int nt = 0; nt < 4; nt++)
                    mma16(acc[mt][nt], af[mt], bf[nt]);
        }
        if (++slot == 3) slot = 0;
    }
    __syncthreads();   // all mma smem reads done before Zs overwrites

    __half* Zs = (__half*)smraw;
    __half* Ps = (__half*)(smraw + OFF_PS);
    float*  znsm = (float*)(smraw + OFF_ZN);   // [128][4]

    // fill Ps: proto[c][colBase..+128] -> Ps[d][c] fp16
    {
        int cc = tid >> 2;
        int dpart = (tid & 3) * 32;
        const float* pr = proto + (size_t)cc * N + colBase + dpart;
        #pragma unroll
        for (int j = 0; j < 8; j++) {
            float4 v = *(const float4*)(pr + j * 4);
            int d = dpart + j * 4;
            Ps[(d + 0) * PS2 + cc] = __float2half_rn(v.x);
            Ps[(d + 1) * PS2 + cc] = __float2half_rn(v.y);
            Ps[(d + 2) * PS2 + cc] = __float2half_rn(v.z);
            Ps[(d + 3) * PS2 + cc] = __float2half_rn(v.w);
        }
    }

    int lg = lane >> 2, lq = lane & 3;

    // epilogue 1: bias add, znorm strip-partials -> znsm, stage z fp16 -> Zs
    #pragma unroll
    for (int mt = 0; mt < 4; mt++) {
        int rl = wm * 64 + mt * 16 + lg;
        float sum0 = 0.f, sum1 = 0.f;
        #pragma unroll
        for (int nt = 0; nt < 4; nt++) {
            int cl = wn * 32 + nt * 8 + lq * 2;
            float bv0 = bias[colBase + cl], bv1 = bias[colBase + cl + 1];
            float v0 = acc[mt][nt][0] + bv0;
            float v1 = acc[mt][nt][1] + bv1;
            float v2 = acc[mt][nt][2] + bv0;
            float v3 = acc[mt][nt][3] + bv1;
            *(__half2*)&Zs[rl * ZS2 + cl]       = __floats2half2_rn(v0, v1);
            *(__half2*)&Zs[(rl + 8) * ZS2 + cl] = __floats2half2_rn(v2, v3);
            sum0 = fmaf(v0, v0, fmaf(v1, v1, sum0));
            sum1 = fmaf(v2, v2, fmaf(v3, v3, sum1));
        }
        sum0 += __shfl_xor_sync(0xFFFFFFFFu, sum0, 1);
        sum0 += __shfl_xor_sync(0xFFFFFFFFu, sum0, 2);
        sum1 += __shfl_xor_sync(0xFFFFFFFFu, sum1, 1);
        sum1 += __shfl_xor_sync(0xFFFFFFFFu, sum1, 2);
        if (lq == 0) {
            znsm[rl * 4 + wn]       = sum0;
            znsm[(rl + 8) * 4 + wn] = sum1;
        }
    }
    __syncthreads();

    // epilogue 2: cross = Zs[128x128] @ Ps^T -> red.add into out
    {
        float cacc[8][4];
        #pragma unroll
        for (int ct = 0; ct < 8; ct++)
            #pragma unroll
            for (int r = 0; r < 4; r++) cacc[ct][r] = 0.0f;

        uint32_t zlm = sbase + (uint32_t)((warp * 16 + r16) * ZS2 + khalf) * 2;
        uint32_t psBase = sbase + OFF_PS;

        #pragma unroll
        for (int kk = 0; kk < 8; kk++) {
            uint32_t afx[4];
            LDSM_X4(afx, zlm + kk * 32);
            #pragma unroll
            for (int ct = 0; ct < 8; ct++) {
                uint32_t bfx[2];
                LDSM_X2T(bfx, psBase +
                    (uint32_t)((kk * 16 + r16) * PS2 + ct * 8) * 2);
                mma16(cacc[ct], afx, bfx);
            }
        }

        int lr0 = warp * 16 + lg;
        float zn0 = znsm[lr0 * 4 + 0] + znsm[lr0 * 4 + 1] +
                    znsm[lr0 * 4 + 2] + znsm[lr0 * 4 + 3];
        float zn1 = znsm[(lr0 + 8) * 4 + 0] + znsm[(lr0 + 8) * 4 + 1] +
                    znsm[(lr0 + 8) * 4 + 2] + znsm[(lr0 + 8) * 4 + 3];

        int r0 = rowBase + lr0;
        #pragma unroll
        for (int ct = 0; ct < 8; ct++) {
            int col = ct * 8 + lq * 2;
            float p0 = 0.25f * pnorm[col];
            float p1 = 0.25f * pnorm[col + 1];
            atomicAdd(out + (size_t)r0 * NWAY + col,
                      2.0f * cacc[ct][0] - zn0 - p0);
            atomicAdd(out + (size_t)r0 * NWAY + col + 1,
                      2.0f * cacc[ct][1] - zn0 - p1);
            atomicAdd(out + (size_t)(r0 + 8) * NWAY + col,
                      2.0f * cacc[ct][2] - zn1 - p0);
            atomicAdd(out + (size_t)(r0 + 8) * NWAY + col + 1,
                      2.0f * cacc[ct][3] - zn1 - p1);
        }
    }
}

// ---------------------------------------------------------------------------
// Host launcher: 4 launches, all on the capture stream.
// ---------------------------------------------------------------------------
extern "C" void kernel_launch(void* const* d_in, const int* in_sizes, int n_in,
                              void* d_out, int out_size) {
    const float* xs = (const float*)d_in[0];
    const void*  ys = d_in[1];
    const float* xq = (const float*)d_in[2];
    const float* W  = (const float*)d_in[3];
    const float* b  = (const float*)d_in[4];

    int S = in_sizes[1];
    int F = in_sizes[0] / S;
    int D = in_sizes[4];
    int Q = in_sizes[2] / F;

    float *p_cls, *p_proto, *p_pnorm, *p_invcnt;
    __half *p_xq16, *p_w16;
    int *p_cnt;
    cudaGetSymbolAddress((void**)&p_cls, g_cls_part);
    cudaGetSymbolAddress((void**)&p_proto, g_proto);
    cudaGetSymbolAddress((void**)&p_pnorm, g_pnorm);
    cudaGetSymbolAddress((void**)&p_invcnt, g_invcnt);
    cudaGetSymbolAddress((void**)&p_cnt, g_cnt);
    cudaGetSymbolAddress((void**)&p_xq16, g_xq16);
    cudaGetSymbolAddress((void**)&p_w16, g_w16);

    cudaFuncSetAttribute(k_mega1,
                         cudaFuncAttributeMaxDynamicSharedMemorySize,
                         MEGA_SMEM);
    cudaFuncSetAttribute(k_proto_tc,
                         cudaFuncAttributeMaxDynamicSharedMemorySize,
                         PROTO_SMEM_FLOATS * 4);
    cudaFuncSetAttribute(gemm_fused,
                         cudaFuncAttributeMaxDynamicSharedMemorySize,
                         GEMM_SMEM);

    // 1. mega prep: cls partial sums + counts + zero proto/out + fp16 cvt
    int n8q = Q * F / 8, n8w = F * D / 8;
    int protoQ4 = NWAY * D / 4;
    int outQ4 = Q * NWAY / 4;
    int nbCls = (F / 256) * NSLAB;                 // 64
    int nbZp = (protoQ4 + 255) / 256;              // 32
    int nbZo = (outQ4 + 255) / 256;                // 1024
    int nbCq = (n8q + 255) / 256;                  // 16384
    int nbCw = (n8w + 255) / 256;                  // 512
    int nbTot = nbCls + 1 + nbZp + nbZo + nbCq + nbCw;
    k_mega1<<<nbTot, 256, MEGA_SMEM>>>(
        xq, p_xq16, n8q, W, p_w16, n8w, xs, ys, S, F,
        p_cls, p_proto, protoQ4, (float*)d_out, outQ4,
        p_cnt, p_invcnt, nbCls, nbZp, nbZo, nbCq);

    // 2. prototypes: proto = (Σ slabs) @ W  (tf32 tensor cores, split-K)
    {
        dim3 grid(D / 128, F / 128);
        k_proto_tc<<<grid, 256, PROTO_SMEM_FLOATS * 4>>>(
            p_cls, W, p_proto, F, D);
    }

    // 3. proto finalize: *invcnt, +bias (non-empty), pnorm
    k_proto_fin<<<NWAY, 128>>>(p_proto, b, p_cnt, p_invcnt, p_pnorm, D);

    // 4. fused fp16 GEMM (BK=64, 3-slot) + full epilogue
    {
        dim3 grid(NC, Q / 128);
        gemm_fused<<<grid, 256, GEMM_SMEM>>>(
            p_xq16, p_w16, b, p_proto, p_pnorm, (float*)d_out, Q, D, F);
    }
}

// round 16
// speedup vs baseline: 1.0823x; 1.0398x over previous
#include <cuda_runtime.h>
#include <cuda_fp16.h>
#include <cstdint>

// ---------------------------------------------------------------------------
// ProtoNet: out[q,c] = -||z_q - proto_c||^2
//   z_q   = xq @ W + b   (fp16 m16n8k16 mma, fp32 accum, cp.async 3-slot
//                         BK=64 pipeline, 4 warps x 64x64 warp tiles)
//   proto = (classsum(xs)/cnt) @ W + b   (tf32 mma.sync, split-K)
//   out   = 2*z.proto^T - ||z||^2 - ||proto||^2  (red.add into d_out)
// 4 launches: mega-prep -> proto_tc -> proto_fin -> gemm_fused(+epilogue)
// Shapes: S=1024, Q=16384, F=2048, D=512, NWAY=64
// ---------------------------------------------------------------------------

#define NWAY 64
#define Q_MAX 16384
#define F_MAX 2048
#define NC 4              // D / 128 column chunks
#define NSLAB 8           // S split for class sums

__device__ __half g_xq16[(size_t)Q_MAX * F_MAX];          // 64 MB
__device__ __half g_w16[F_MAX * 512];                     // 2 MB
__device__ float g_cls_part[NSLAB * NWAY * F_MAX];        // 4 MB
__device__ float g_proto[NWAY * 512];                     // 128 KB
__device__ float g_pnorm[NWAY];
__device__ float g_invcnt[NWAY];
__device__ int   g_cnt[NWAY];

// single dynamic-smem symbol shared by all kernels
extern __shared__ char dyn_smem[];

// ---------------------------------------------------------------------------
// helpers
// ---------------------------------------------------------------------------
__device__ __forceinline__ float f2tf32(float x) {
    unsigned u;
    asm("cvt.rna.tf32.f32 %0, %1;" : "=r"(u) : "f"(x));
    return __uint_as_float(u);
}

__device__ __forceinline__ void mma8(float* d, const float* a, const float* b) {
    const unsigned* A = reinterpret_cast<const unsigned*>(a);
    const unsigned* B = reinterpret_cast<const unsigned*>(b);
    asm volatile(
        "mma.sync.aligned.m16n8k8.row.col.f32.tf32.tf32.f32 "
        "{%0,%1,%2,%3}, {%4,%5,%6,%7}, {%8,%9}, {%0,%1,%2,%3};\n"
        : "+f"(d[0]), "+f"(d[1]), "+f"(d[2]), "+f"(d[3])
        : "r"(A[0]), "r"(A[1]), "r"(A[2]), "r"(A[3]), "r"(B[0]), "r"(B[1]));
}

__device__ __forceinline__ void mma16(float* d, const uint32_t* a,
                                      const uint32_t* b) {
    asm volatile(
        "mma.sync.aligned.m16n8k16.row.col.f32.f16.f16.f32 "
        "{%0,%1,%2,%3}, {%4,%5,%6,%7}, {%8,%9}, {%0,%1,%2,%3};\n"
        : "+f"(d[0]), "+f"(d[1]), "+f"(d[2]), "+f"(d[3])
        : "r"(a[0]), "r"(a[1]), "r"(a[2]), "r"(a[3]), "r"(b[0]), "r"(b[1]));
}

#define LDSM_X4(r, addr)                                                      \
    asm volatile("ldmatrix.sync.aligned.m8n8.x4.shared.b16 {%0,%1,%2,%3}, [%4];" \
                 : "=r"((r)[0]), "=r"((r)[1]), "=r"((r)[2]), "=r"((r)[3])     \
                 : "r"(addr))

#define LDSM_X2T(r, addr)                                                     \
    asm volatile("ldmatrix.sync.aligned.m8n8.x2.trans.shared.b16 {%0,%1}, [%2];" \
                 : "=r"((r)[0]), "=r"((r)[1]) : "r"(addr))

#define CP_ASYNC16(dst, src)                                                  \
    asm volatile("cp.async.cg.shared.global [%0], [%1], 16;"                  \
                 :: "r"(dst), "l"(src) : "memory")
#define CP_COMMIT() asm volatile("cp.async.commit_group;" ::: "memory")
#define CP_WAIT1()  asm volatile("cp.async.wait_group 1;" ::: "memory")

__device__ __forceinline__ uint32_t smem_u32(const void* p) {
    uint32_t a;
    asm("{ .reg .u64 t; cvta.to.shared.u64 t, %1; cvt.u32.u64 %0, t; }"
        : "=r"(a) : "l"(p));
    return a;
}

__device__ __forceinline__ void cvt8_store(const float* x, __half* y,
                                           size_t idx) {
    const float4* p = (const float4*)x + idx * 2;
    float4 a = p[0], b = p[1];
    __half2 h[4];
    h[0] = __floats2half2_rn(a.x, a.y);
    h[1] = __floats2half2_rn(a.z, a.w);
    h[2] = __floats2half2_rn(b.x, b.y);
    h[3] = __floats2half2_rn(b.z, b.w);
    *(uint4*)(y + idx * 8) = *(uint4*)h;
}

// ---------------------------------------------------------------------------
// k_mega1: ONE launch doing all independent prep work, dispatched by block.
// ---------------------------------------------------------------------------
#define MEGA_SMEM 66560

__global__ __launch_bounds__(256) void k_mega1(
    const float* __restrict__ xq, __half* __restrict__ xq16, int n8q,
    const float* __restrict__ Wf, __half* __restrict__ w16, int n8w,
    const float* __restrict__ xs, const void* __restrict__ ys, int S, int F,
    float* __restrict__ cls_part,
    float* __restrict__ proto, int protoQ4,
    float* __restrict__ out, int outQ4,
    int* __restrict__ cnt_out, float* __restrict__ invcnt,
    int nbCls, int nbZp, int nbZo, int nbCq)
{
    char* sm = dyn_smem;
    int bx = blockIdx.x, tid = threadIdx.x;

    if (bx < nbCls) {                       // ---- class partial sums ----
        float* acc = (float*)sm;            // [64][256]
        int* sys = (int*)(sm + 65536);      // [128]
        int* flag = sys + 128;
        int slice = bx & (NSLAB - 1), fb = bx >> 3;
        int chunk = S / NSLAB, s0 = slice * chunk;

        if (tid == 0) *flag = 0;
        __syncthreads();
        const int* w32 = (const int*)ys;
        for (int j = 1 + 2 * tid; j < S; j += 512)
            if (w32[j] != 0) *flag = 1;     // benign race
        __syncthreads();
        int is64 = !*flag;
        const long long* w64 = (const long long*)ys;
        for (int i = tid; i < chunk; i += 256)
            sys[i] = is64 ? (int)w64[s0 + i] : w32[s0 + i];
        #pragma unroll
        for (int c = 0; c < NWAY; c++) acc[c * 256 + tid] = 0.0f;
        __syncthreads();

        int f = fb * 256 + tid;
        #pragma unroll 4
        for (int i = 0; i < chunk; i++)
            acc[sys[i] * 256 + tid] += xs[(size_t)(s0 + i) * F + f];

        #pragma unroll
        for (int c = 0; c < NWAY; c++)
            cls_part[(size_t)(slice * NWAY + c) * F + f] = acc[c * 256 + tid];
        return;
    }
    bx -= nbCls;
    if (bx == 0) {                          // ---- label counts ----
        int* scnt = (int*)sm;
        int* flag = scnt + NWAY;
        if (tid == 0) *flag = 0;
        if (tid < NWAY) scnt[tid] = 0;
        __syncthreads();
        const int* w32 = (const int*)ys;
        for (int j = 1 + 2 * tid; j < S; j += 512)
            if (w32[j] != 0) *flag = 1;
        __syncthreads();
        int is64 = !*flag;
        const long long* w64 = (const long long*)ys;
        for (int i = tid; i < S; i += 256) {
            int c = is64 ? (int)w64[i] : w32[i];
            atomicAdd(&scnt[c], 1);
        }
        __syncthreads();
        if (tid < NWAY) {
            int c = scnt[tid];
            cnt_out[tid] = c;
            invcnt[tid] = 1.0f / (float)(c > 0 ? c : 1);
        }
        return;
    }
    bx -= 1;
    if (bx < nbZp) {                        // ---- zero proto ----
        int idx = bx * 256 + tid;
        if (idx < protoQ4)
            ((float4*)proto)[idx] = make_float4(0.f, 0.f, 0.f, 0.f);
        return;
    }
    bx -= nbZp;
    if (bx < nbZo) {                        // ---- zero out ----
        int idx = bx * 256 + tid;
        if (idx < outQ4)
            ((float4*)out)[idx] = make_float4(0.f, 0.f, 0.f, 0.f);
        return;
    }
    bx -= nbZo;
    if (bx < nbCq) {                        // ---- cvt xq ----
        size_t i = (size_t)bx * 256 + tid;
        if (i < (size_t)n8q) cvt8_store(xq, xq16, i);
        return;
    }
    bx -= nbCq;
    {                                       // ---- cvt W ----
        size_t i = (size_t)bx * 256 + tid;
        if (i < (size_t)n8w) cvt8_store(Wf, w16, i);
    }
}

// ---------------------------------------------------------------------------
// k_proto_tc: proto += (Σ_slab cls_part) @ W tile, tf32 mma.sync, split-K.
// ---------------------------------------------------------------------------
#define PAS 132
#define PWS 136
#define PROTO_SMEM_FLOATS (64 * PAS + 128 * PWS)

__global__ __launch_bounds__(256) void k_proto_tc(
    const float* __restrict__ cls_part, const float* __restrict__ W,
    float* __restrict__ proto, int F, int D)
{
    float* smf = (float*)dyn_smem;
    float* As = smf;
    float* Ws = smf + 64 * PAS;

    int tid  = threadIdx.x;
    int warp = tid >> 5, lane = tid & 31;
    int wm = warp & 1;
    int wn = warp >> 1;
    int colBase = blockIdx.x * 128;
    int k0 = blockIdx.y * 128;

    {   // A slice: 64 rows x 128 k, summed over NSLAB slabs, tf32
        int row = tid >> 2;
        int kp  = (tid & 3) * 32;
        const float* ap = cls_part + (size_t)row * F + k0 + kp;
        const size_t slab = (size_t)NWAY * F;
        #pragma unroll
        for (int j = 0; j < 8; j++) {
            float4 v = make_float4(0.f, 0.f, 0.f, 0.f);
            #pragma unroll
            for (int s = 0; s < NSLAB; s++) {
                float4 u = *(const float4*)(ap + s * slab + j * 4);
                v.x += u.x; v.y += u.y; v.z += u.z; v.w += u.w;
            }
            float4 t;
            t.x = f2tf32(v.x); t.y = f2tf32(v.y);
            t.z = f2tf32(v.z); t.w = f2tf32(v.w);
            *(float4*)&As[row * PAS + kp + j * 4] = t;
        }
    }
    {   // W slice: 128 k x 128 cols, tf32
        int kr = tid >> 1;
        int cp = (tid & 1) * 64;
        const float* wp = W + (size_t)(k0 + kr) * D + colBase + cp;
        #pragma unroll
        for (int j = 0; j < 16; j++) {
            float4 v = *(const float4*)(wp + j * 4);
            float4 t;
            t.x = f2tf32(v.x); t.y = f2tf32(v.y);
            t.z = f2tf32(v.z); t.w = f2tf32(v.w);
            *(float4*)&Ws[kr * PWS + cp + j * 4] = t;
        }
    }
    __syncthreads();

    int lg = lane >> 2;
    int lq = lane & 3;

    float acc[2][4][4];
    #pragma unroll
    for (int i = 0; i < 2; i++)
        #pragma unroll
        for (int j = 0; j < 4; j++)
            #pragma unroll
            for (int r = 0; r < 4; r++) acc[i][j][r] = 0.0f;

    int aoff[2], boff[4];
    #pragma unroll
    for (int mt = 0; mt < 2; mt++)
        aoff[mt] = (wm * 32 + mt * 16 + lg) * PAS + lq;
    #pragma unroll
    for (int nt = 0; nt < 4; nt++)
        boff[nt] = lq * PWS + wn * 32 + nt * 8 + lg;

    #pragma unroll 4
    for (int kk = 0; kk < 128; kk += 8) {
        float af[2][4], bf[4][2];
        #pragma unroll
        for (int mt = 0; mt < 2; mt++) {
            const float* base = &As[aoff[mt] + kk];
            af[mt][0] = base[0];
            af[mt][1] = base[8 * PAS];
            af[mt][2] = base[4];
            af[mt][3] = base[8 * PAS + 4];
        }
        #pragma unroll
        for (int nt = 0; nt < 4; nt++) {
            const float* base = &Ws[boff[nt] + kk * PWS];
            bf[nt][0] = base[0];
            bf[nt][1] = base[4 * PWS];
        }
        #pragma unroll
        for (int mt = 0; mt < 2; mt++)
            #pragma unroll
            for (int nt = 0; nt < 4; nt++)
                mma8(acc[mt][nt], af[mt], bf[nt]);
    }

    #pragma unroll
    for (int mt = 0; mt < 2; mt++) {
        int r = wm * 32 + mt * 16 + lg;
        #pragma unroll
        for (int nt = 0; nt < 4; nt++) {
            int d = colBase + wn * 32 + nt * 8 + lq * 2;
            atomicAdd(&proto[(size_t)r * D + d],       acc[mt][nt][0]);
            atomicAdd(&proto[(size_t)r * D + d + 1],   acc[mt][nt][1]);
            atomicAdd(&proto[(size_t)(r + 8) * D + d],     acc[mt][nt][2]);
            atomicAdd(&proto[(size_t)(r + 8) * D + d + 1], acc[mt][nt][3]);
        }
    }
}

// ---------------------------------------------------------------------------
// k_proto_fin: proto = proto*invcnt + bias (non-empty only), pnorm[c]
// ---------------------------------------------------------------------------
__global__ void k_proto_fin(float* __restrict__ proto,
                            const float* __restrict__ bias,
                            const int* __restrict__ cnt,
                            const float* __restrict__ invcnt,
                            float* __restrict__ pnorm, int D) {
    __shared__ float red[128];
    int c = blockIdx.x;
    int tid = threadIdx.x;
    bool nonempty = cnt[c] > 0;
    float ic = invcnt[c];
    float s = 0.f;
    for (int d = tid; d < D; d += blockDim.x) {
        float v = proto[(size_t)c * D + d] * ic + (nonempty ? bias[d] : 0.0f);
        proto[(size_t)c * D + d] = v;
        s = fmaf(v, v, s);
    }
    red[tid] = s;
    __syncthreads();
    for (int o = 64; o > 0; o >>= 1) {
        if (tid < o) red[tid] += red[tid + o];
        __syncthreads();
    }
    if (tid == 0) pnorm[c] = red[0];
}

// ---------------------------------------------------------------------------
// gemm_fused: fp16 mma, BK=64, 3-slot cp.async pipeline, 128 threads
// (4 warps, 64x64 warp tiles -> ldsm traffic cut 33% vs 8x(64x32)).
// Fused final epilogue (red.add into pre-zeroed out).
// SMEM slots: slot s at s*SLOT_B: A 128x72h (18432 B), B 64x136h (17408 B).
// Epilogue (overlaps slots): Zs 128x136h, Ps at 34816, znsm at 53248.
// ---------------------------------------------------------------------------
#define BK 64
#define AS2 72      // halfs per A row (64 + 8) ; 144 B row
#define BS2 136     // halfs per B k-row (128 + 8)
#define ZS2 136
#define PS2 72
#define A_BYTES (128 * AS2 * 2)     // 18432
#define B_BYTES (BK * BS2 * 2)      // 17408
#define SLOT_B  (A_BYTES + B_BYTES) // 35840
#define OFF_PS  34816
#define OFF_ZN  (OFF_PS + 128 * PS2 * 2)     // 53248
#define GEMM_SMEM (3 * SLOT_B)               // 107520

__global__ __launch_bounds__(128, 2) void gemm_fused(
    const __half* __restrict__ A, const __half* __restrict__ Wh,
    const float* __restrict__ bias, const float* __restrict__ proto,
    const float* __restrict__ pnorm, float* __restrict__ out,
    int M, int N, int K)
{
    char* smraw = dyn_smem;
    const uint32_t sbase = smem_u32(smraw);

    int tid  = threadIdx.x;
    int warp = tid >> 5, lane = tid & 31;
    int wm = warp & 1;        // 0..1  (64-row half)
    int wn = warp >> 1;       // 0..1  (64-col half)
    int cx = blockIdx.x;
    int rowBase = blockIdx.y * 128;
    int colBase = cx * 128;

    const __half* aG = A + (size_t)rowBase * K;
    const __half* bG = Wh + colBase;

    float acc[4][8][4];
    #pragma unroll
    for (int i = 0; i < 4; i++)
        #pragma unroll
        for (int j = 0; j < 8; j++)
            #pragma unroll
            for (int r = 0; r < 4; r++) acc[i][j][r] = 0.0f;

    int r16 = lane & 15, khalf = (lane >> 4) * 8;
    uint32_t aFragOff[4], bFragOff[8];
    #pragma unroll
    for (int mt = 0; mt < 4; mt++)
        aFragOff[mt] = (uint32_t)((wm * 64 + mt * 16 + r16) * AS2 + khalf) * 2;
    #pragma unroll
    for (int nt = 0; nt < 8; nt++)
        bFragOff[nt] = (uint32_t)(r16 * BS2 + wn * 64 + nt * 8) * 2;

    const int nIt = K / BK;   // 32

    // issue one BK=64 slot's loads: 8 x 16B per operand per thread
    auto issue_slot = [&](int slot, int k0) {
        uint32_t aBase = sbase + slot * SLOT_B;
        uint32_t bBase = aBase + A_BYTES;
        #pragma unroll
        for (int j = 0; j < 8; j++) {
            int ch = tid + j * 128;
            int ar = ch >> 3, ao = (ch & 7) * 8;     // A: 128 rows x 8 chunks
            int br = ch >> 4, bo = (ch & 15) * 8;    // B: 64 rows x 16 chunks
            CP_ASYNC16(aBase + (uint32_t)(ar * AS2 + ao) * 2,
                       aG + (size_t)ar * K + k0 + ao);
            CP_ASYNC16(bBase + (uint32_t)(br * BS2 + bo) * 2,
                       bG + (size_t)(k0 + br) * N + bo);
        }
    };

    // prologue: fill slots 0,1
    issue_slot(0, 0);
    CP_COMMIT();
    issue_slot(1, BK);
    CP_COMMIT();

    int slot = 0;
    for (int it = 0; it < nIt; ++it) {
        CP_WAIT1();
        __syncthreads();

        if (it + 2 < nIt) {
            int s2 = slot + 2; if (s2 >= 3) s2 -= 3;
            issue_slot(s2, (it + 2) * BK);
        }
        CP_COMMIT();

        uint32_t aB = sbase + slot * SLOT_B;
        uint32_t bB = aB + A_BYTES;
        #pragma unroll
        for (int ks = 0; ks < 4; ks++) {       // four k16 steps in BK=64
            uint32_t af[4][4], bf[8][2];
            #pragma unroll
            for (int mt = 0; mt < 4; mt++)
                LDSM_X4(af[mt], aB + aFragOff[mt] + ks * 32);
            #pragma unroll
            for (int nt = 0; nt < 8; nt++)
                LDSM_X2T(bf[nt], bB + bFragOff[nt] + ks * 16 * BS2 * 2);
            #pragma unroll
            for (int mt = 0; mt < 4; mt++)
                #pragma unroll
                for (int nt = 0; nt < 8; nt++)
                    mma16(acc[mt][nt], af[mt], bf[nt]);
        }
        if (++slot == 3) slot = 0;
    }
    __syncthreads();   // all mma smem reads done before Zs overwrites

    __half* Zs = (__half*)smraw;
    __half* Ps = (__half*)(smraw + OFF_PS);
    float*  znsm = (float*)(smraw + OFF_ZN);   // [128][2]

    // fill Ps: proto[c][colBase..+128] -> Ps[d][c] fp16
    {
        int cc = tid >> 1;
        int dpart = (tid & 1) * 64;
        const float* pr = proto + (size_t)cc * N + colBase + dpart;
        #pragma unroll
        for (int j = 0; j < 16; j++) {
            float4 v = *(const float4*)(pr + j * 4);
            int d = dpart + j * 4;
            Ps[(d + 0) * PS2 + cc] = __float2half_rn(v.x);
            Ps[(d + 1) * PS2 + cc] = __float2half_rn(v.y);
            Ps[(d + 2) * PS2 + cc] = __float2half_rn(v.z);
            Ps[(d + 3) * PS2 + cc] = __float2half_rn(v.w);
        }
    }

    int lg = lane >> 2, lq = lane & 3;

    // epilogue 1: bias add, znorm half-partials -> znsm, stage z fp16 -> Zs
    #pragma unroll
    for (int mt = 0; mt < 4; mt++) {
        int rl = wm * 64 + mt * 16 + lg;
        float sum0 = 0.f, sum1 = 0.f;
        #pragma unroll
        for (int nt = 0; nt < 8; nt++) {
            int cl = wn * 64 + nt * 8 + lq * 2;
            float bv0 = bias[colBase + cl], bv1 = bias[colBase + cl + 1];
            float v0 = acc[mt][nt][0] + bv0;
            float v1 = acc[mt][nt][1] + bv1;
            float v2 = acc[mt][nt][2] + bv0;
            float v3 = acc[mt][nt][3] + bv1;
            *(__half2*)&Zs[rl * ZS2 + cl]       = __floats2half2_rn(v0, v1);
            *(__half2*)&Zs[(rl + 8) * ZS2 + cl] = __floats2half2_rn(v2, v3);
            sum0 = fmaf(v0, v0, fmaf(v1, v1, sum0));
            sum1 = fmaf(v2, v2, fmaf(v3, v3, sum1));
        }
        sum0 += __shfl_xor_sync(0xFFFFFFFFu, sum0, 1);
        sum0 += __shfl_xor_sync(0xFFFFFFFFu, sum0, 2);
        sum1 += __shfl_xor_sync(0xFFFFFFFFu, sum1, 1);
        sum1 += __shfl_xor_sync(0xFFFFFFFFu, sum1, 2);
        if (lq == 0) {
            znsm[rl * 2 + wn]       = sum0;
            znsm[(rl + 8) * 2 + wn] = sum1;
        }
    }
    __syncthreads();

    // epilogue 2: cross = Zs[128x128] @ Ps^T -> red.add into out
    // warp w owns rows w*32 .. w*32+31 (2 m-frags x 8 ct)
    {
        float cacc[2][8][4];
        #pragma unroll
        for (int mf = 0; mf < 2; mf++)
            #pragma unroll
            for (int ct = 0; ct < 8; ct++)
                #pragma unroll
                for (int r = 0; r < 4; r++) cacc[mf][ct][r] = 0.0f;

        uint32_t zlm[2];
        #pragma unroll
        for (int mf = 0; mf < 2; mf++)
            zlm[mf] = sbase +
                (uint32_t)((warp * 32 + mf * 16 + r16) * ZS2 + khalf) * 2;
        uint32_t psBase = sbase + OFF_PS;

        #pragma unroll
        for (int kk = 0; kk < 8; kk++) {
            uint32_t afx[2][4];
            #pragma unroll
            for (int mf = 0; mf < 2; mf++)
                LDSM_X4(afx[mf], zlm[mf] + kk * 32);
            #pragma unroll
            for (int ct = 0; ct < 8; ct++) {
                uint32_t bfx[2];
                LDSM_X2T(bfx, psBase +
                    (uint32_t)((kk * 16 + r16) * PS2 + ct * 8) * 2);
                #pragma unroll
                for (int mf = 0; mf < 2; mf++)
                    mma16(cacc[mf][ct], afx[mf], bfx);
            }
        }

        #pragma unroll
        for (int mf = 0; mf < 2; mf++) {
            int lr0 = warp * 32 + mf * 16 + lg;
            float zn0 = znsm[lr0 * 2 + 0] + znsm[lr0 * 2 + 1];
            float zn1 = znsm[(lr0 + 8) * 2 + 0] + znsm[(lr0 + 8) * 2 + 1];
            int r0 = rowBase + lr0;
            #pragma unroll
            for (int ct = 0; ct < 8; ct++) {
                int col = ct * 8 + lq * 2;
                float p0 = 0.25f * pnorm[col];
                float p1 = 0.25f * pnorm[col + 1];
                atomicAdd(out + (size_t)r0 * NWAY + col,
                          2.0f * cacc[mf][ct][0] - zn0 - p0);
                atomicAdd(out + (size_t)r0 * NWAY + col + 1,
                          2.0f * cacc[mf][ct][1] - zn0 - p1);
                atomicAdd(out + (size_t)(r0 + 8) * NWAY + col,
                          2.0f * cacc[mf][ct][2] - zn1 - p0);
                atomicAdd(out + (size_t)(r0 + 8) * NWAY + col + 1,
                          2.0f * cacc[mf][ct][3] - zn1 - p1);
            }
        }
    }
}

// ---------------------------------------------------------------------------
// Host launcher: 4 launches, all on the capture stream.
// ---------------------------------------------------------------------------
extern "C" void kernel_launch(void* const* d_in, const int* in_sizes, int n_in,
                              void* d_out, int out_size) {
    const float* xs = (const float*)d_in[0];
    const void*  ys = d_in[1];
    const float* xq = (const float*)d_in[2];
    const float* W  = (const float*)d_in[3];
    const float* b  = (const float*)d_in[4];

    int S = in_sizes[1];
    int F = in_sizes[0] / S;
    int D = in_sizes[4];
    int Q = in_sizes[2] / F;

    float *p_cls, *p_proto, *p_pnorm, *p_invcnt;
    __half *p_xq16, *p_w16;
    int *p_cnt;
    cudaGetSymbolAddress((void**)&p_cls, g_cls_part);
    cudaGetSymbolAddress((void**)&p_proto, g_proto);
    cudaGetSymbolAddress((void**)&p_pnorm, g_pnorm);
    cudaGetSymbolAddress((void**)&p_invcnt, g_invcnt);
    cudaGetSymbolAddress((void**)&p_cnt, g_cnt);
    cudaGetSymbolAddress((void**)&p_xq16, g_xq16);
    cudaGetSymbolAddress((void**)&p_w16, g_w16);

    cudaFuncSetAttribute(k_mega1,
                         cudaFuncAttributeMaxDynamicSharedMemorySize,
                         MEGA_SMEM);
    cudaFuncSetAttribute(k_proto_tc,
                         cudaFuncAttributeMaxDynamicSharedMemorySize,
                         PROTO_SMEM_FLOATS * 4);
    cudaFuncSetAttribute(gemm_fused,
                         cudaFuncAttributeMaxDynamicSharedMemorySize,
                         GEMM_SMEM);

    // 1. mega prep: cls partial sums + counts + zero proto/out + fp16 cvt
    int n8q = Q * F / 8, n8w = F * D / 8;
    int protoQ4 = NWAY * D / 4;
    int outQ4 = Q * NWAY / 4;
    int nbCls = (F / 256) * NSLAB;                 // 64
    int nbZp = (protoQ4 + 255) / 256;              // 32
    int nbZo = (outQ4 + 255) / 256;                // 1024
    int nbCq = (n8q + 255) / 256;                  // 16384
    int nbCw = (n8w + 255) / 256;                  // 512
    int nbTot = nbCls + 1 + nbZp + nbZo + nbCq + nbCw;
    k_mega1<<<nbTot, 256, MEGA_SMEM>>>(
        xq, p_xq16, n8q, W, p_w16, n8w, xs, ys, S, F,
        p_cls, p_proto, protoQ4, (float*)d_out, outQ4,
        p_cnt, p_invcnt, nbCls, nbZp, nbZo, nbCq);

    // 2. prototypes: proto = (Σ slabs) @ W  (tf32 tensor cores, split-K)
    {
        dim3 grid(D / 128, F / 128);
        k_proto_tc<<<grid, 256, PROTO_SMEM_FLOATS * 4>>>(
            p_cls, W, p_proto, F, D);
    }

    // 3. proto finalize: *invcnt, +bias (non-empty), pnorm
    k_proto_fin<<<NWAY, 128>>>(p_proto, b, p_cnt, p_invcnt, p_pnorm, D);

    // 4. fused fp16 GEMM (BK=64, 3-slot, 4 warps x 64x64) + full epilogue
    {
        dim3 grid(NC, Q / 128);
        gemm_fused<<<grid, 128, GEMM_SMEM>>>(
            p_xq16, p_w16, b, p_proto, p_pnorm, (float*)d_out, Q, D, F);
    }
}